// round 17
// baseline (speedup 1.0000x reference)
#include <cuda_runtime.h>

// NeighborList: all i<j pairs, minimum-image PBC, cutoff mask.
// Output (float32): [0,P) pair_i | [P,2P) pair_j | [2P,5P) deltas[P,3] | [5P,6P) dist

#define MAXN 8192
#define TPB  256
#define UPT  8          // pairs per thread (P % (UPT*TPB) == 0 for n=4096)

__device__ float g_x[MAXN], g_y[MAXN], g_z[MAXN];
__device__ float g_inv[9];
__device__ float g_cellm[9];
__device__ float g_diag[6];   // {inv00,inv11,inv22, cell00,cell11,cell22}; zeros if no PBC
__device__ int   g_general;   // 1 = non-diagonal cell (rare path)

// Fused prep: thread (0,0) inverts/classifies the cell; all threads transpose xyz -> SoA.
__global__ void prep_kernel(const float* __restrict__ xyz,
                            const float* __restrict__ cell, int n) {
    const int k = blockIdx.x * blockDim.x + threadIdx.x;
    if (k < n) {
        g_x[k] = xyz[3 * k + 0];
        g_y[k] = xyz[3 * k + 1];
        g_z[k] = xyz[3 * k + 2];
    }
    if (blockIdx.x == 0 && threadIdx.x == 0) {
        bool zero = true;
        float c[9];
#pragma unroll
        for (int q = 0; q < 9; q++) {
            c[q] = cell[q];
            if (c[q] != 0.0f) zero = false;
        }
        if (zero) {
            c[0] = c[4] = c[8] = 1.0f;
            c[1] = c[2] = c[3] = c[5] = c[6] = c[7] = 0.0f;
        }
#pragma unroll
        for (int q = 0; q < 9; q++) g_cellm[q] = c[q];

        float a = c[0], b = c[1], cc = c[2];
        float d = c[3], e = c[4], f  = c[5];
        float g = c[6], h = c[7], i  = c[8];
        float A =  (e * i - f * h);
        float B = -(d * i - f * g);
        float C =  (d * h - e * g);
        float det = a * A + b * B + cc * C;
        float invdet = 1.0f / det;
        g_inv[0] = A * invdet;
        g_inv[1] = -(b * i - cc * h) * invdet;
        g_inv[2] =  (b * f - cc * e) * invdet;
        g_inv[3] = B * invdet;
        g_inv[4] =  (a * i - cc * g) * invdet;
        g_inv[5] = -(a * f - cc * d) * invdet;
        g_inv[6] = C * invdet;
        g_inv[7] = -(a * h - b * g) * invdet;
        g_inv[8] =  (a * e - b * d) * invdet;

        const bool diag = (c[1] == 0.0f) && (c[2] == 0.0f) && (c[3] == 0.0f) &&
                          (c[5] == 0.0f) && (c[6] == 0.0f) && (c[7] == 0.0f);
        if (zero) {
            g_diag[0] = g_diag[1] = g_diag[2] = 0.0f;   // wrap becomes exact no-op
            g_diag[3] = g_diag[4] = g_diag[5] = 0.0f;
        } else {
            g_diag[0] = g_inv[0]; g_diag[1] = g_inv[4]; g_diag[2] = g_inv[8];
            g_diag[3] = c[0];     g_diag[4] = c[4];     g_diag[5] = c[8];
        }
        g_general = (!zero && !diag) ? 1 : 0;
    }
}

__device__ __forceinline__ unsigned tri_off(unsigned i, unsigned T) {
    return (i * (T - i)) >> 1;   // i*(2n-1-i)/2
}

__device__ __forceinline__ float fast_sqrt(float x) {
    float r;
    asm("sqrt.approx.f32 %0, %1;" : "=f"(r) : "f"(x));
    return r;
}

__global__ void __launch_bounds__(TPB)
nl_kernel(float* __restrict__ out, int n, unsigned P) {
    const unsigned t = blockIdx.x * TPB + threadIdx.x;
    const unsigned p = (unsigned)UPT * t;
    if (p >= P) return;

    const unsigned T = 2u * (unsigned)n - 1u;

    // ---- unrank p -> (i, j), once per UPT pairs ----
    const unsigned D = T * T - 8u * p;
    const float s = sqrtf((float)D);
    int i = (int)(((float)T - s) * 0.5f);
    if (i < 0) i = 0;
    if (i > n - 2) i = n - 2;
    unsigned offi = tri_off((unsigned)i, T);
    while (offi > p) { i--; offi = tri_off((unsigned)i, T); }
    unsigned rowend = tri_off((unsigned)(i + 1), T);
    while (rowend <= p && i < n - 2) {
        i++; offi = rowend; rowend = tri_off((unsigned)(i + 1), T);
    }
    int j = i + 1 + (int)(p - offi);

    // ---- hoisted state: 6 diag scalars (zeros => exact no-op wrap) ----
    const int general = g_general;
    const float d0 = g_diag[0], d4 = g_diag[1], d8 = g_diag[2];
    const float e0 = g_diag[3], e4 = g_diag[4], e8 = g_diag[5];

    float xi = g_x[i], yi = g_y[i], zi = g_z[i];

    float oi[UPT], oj[UPT], od[UPT], del[3 * UPT];
    const unsigned nv = (P - p < (unsigned)UPT) ? (P - p) : (unsigned)UPT;

#pragma unroll
    for (int k = 0; k < UPT; k++) {
        if ((unsigned)k >= nv) { oi[k] = oj[k] = od[k] = 0.0f;
                                 del[3*k] = del[3*k+1] = del[3*k+2] = 0.0f; continue; }
        if (p + (unsigned)k == rowend) {        // row crossing (rare)
            i++; j = i + 1;
            rowend = tri_off((unsigned)(i + 1), T);
            xi = g_x[i]; yi = g_y[i]; zi = g_z[i];
        }

        float dx = xi - g_x[j];
        float dy = yi - g_y[j];
        float dz = zi - g_z[j];

        if (!general) {
            // diagonal (or no) PBC: per-axis wrap; zeros make this an exact no-op
            dx -= rintf(dx * d0) * e0;          // jnp.round = half-to-even = rintf
            dy -= rintf(dy * d4) * e4;
            dz -= rintf(dz * d8) * e8;
        } else {
            // rare general-cell path: volatile loads, cannot be hoisted -> no reg cost
            volatile const float* vi9 = g_inv;
            volatile const float* vc9 = g_cellm;
            const float f0 = dx * vi9[0] + dy * vi9[3] + dz * vi9[6];
            const float f1 = dx * vi9[1] + dy * vi9[4] + dz * vi9[7];
            const float f2 = dx * vi9[2] + dy * vi9[5] + dz * vi9[8];
            const float r0 = rintf(f0);
            const float r1 = rintf(f1);
            const float r2 = rintf(f2);
            dx -= r0 * vc9[0] + r1 * vc9[3] + r2 * vc9[6];
            dy -= r0 * vc9[1] + r1 * vc9[4] + r2 * vc9[7];
            dz -= r0 * vc9[2] + r1 * vc9[5] + r2 * vc9[8];
        }

        const float dist = fast_sqrt(dx * dx + dy * dy + dz * dz);
        const bool m = (dist <= 5.0f);

        oi[k] = m ? (float)i : -1.0f;
        oj[k] = m ? (float)j : -1.0f;
        od[k] = m ? dist : 0.0f;
        del[3*k + 0] = m ? dx : 0.0f;
        del[3*k + 1] = m ? dy : 0.0f;
        del[3*k + 2] = m ? dz : 0.0f;
        j++;
    }

    if (nv == (unsigned)UPT) {
        // All 16B-aligned: P % 8 == 0, p % 8 == 0. Plain STG.128 (NO stcs).
#pragma unroll
        for (int q = 0; q < UPT / 4; q++) {
            *reinterpret_cast<float4*>(out + p + 4 * q) =
                make_float4(oi[4*q], oi[4*q+1], oi[4*q+2], oi[4*q+3]);
            *reinterpret_cast<float4*>(out + (size_t)P + p + 4 * q) =
                make_float4(oj[4*q], oj[4*q+1], oj[4*q+2], oj[4*q+3]);
            *reinterpret_cast<float4*>(out + 5 * (size_t)P + p + 4 * q) =
                make_float4(od[4*q], od[4*q+1], od[4*q+2], od[4*q+3]);
        }
        float* db = out + 2 * (size_t)P + 3 * (size_t)p;   // byte off 8P+96t, 16B-aligned
#pragma unroll
        for (int q = 0; q < (3 * UPT) / 4; q++) {
            *reinterpret_cast<float4*>(db + 4 * q) =
                make_float4(del[4*q], del[4*q+1], del[4*q+2], del[4*q+3]);
        }
    } else {
        for (unsigned k = 0; k < nv; k++) {
            out[p + k]                 = oi[k];
            out[(size_t)P + p + k]     = oj[k];
            out[5 * (size_t)P + p + k] = od[k];
            out[2 * (size_t)P + 3 * ((size_t)p + k) + 0] = del[3*k + 0];
            out[2 * (size_t)P + 3 * ((size_t)p + k) + 1] = del[3*k + 1];
            out[2 * (size_t)P + 3 * ((size_t)p + k) + 2] = del[3*k + 2];
        }
    }
}

extern "C" void kernel_launch(void* const* d_in, const int* in_sizes, int n_in,
                              void* d_out, int out_size) {
    const float* xyz  = (const float*)d_in[0];
    const float* cell = (const float*)d_in[1];
    if (n_in >= 2 && in_sizes[0] == 9 && in_sizes[1] != 9) {
        const float* t = xyz; xyz = cell; cell = t;
    }
    const int n = (in_sizes[0] == 9 && n_in >= 2) ? in_sizes[1] / 3 : in_sizes[0] / 3;
    const unsigned P = (unsigned)((size_t)n * (size_t)(n - 1) / 2);

    prep_kernel<<<(n + TPB - 1) / TPB, TPB>>>(xyz, cell, n);

    const unsigned nthreads = (P + UPT - 1) / UPT;
    const unsigned blocks = (nthreads + TPB - 1) / TPB;
    nl_kernel<<<blocks, TPB>>>((float*)d_out, n, P);
}